// round 3
// baseline (speedup 1.0000x reference)
#include <cuda_runtime.h>
#include <cstdint>
#include <cstddef>

// Problem constants
#define BB 64      // batch
#define TT 96      // time steps
#define FF 2048    // feature dim
#define HH 2048    // hidden dim
#define G4 8192    // 4*H

// Output layout (flattened tuple: hidden(pred), cell(pred_c), utility, watch)
#define OFF_HID 0
#define OFF_CEL (TT*BB*2)            // 12288
#define OFF_UTL (2*TT*BB*2)          // 24576
#define OFF_WCH (2*TT*BB*2 + TT*BB)  // 30720

// ---------------- device scratch (no allocs allowed) ----------------
__device__ float g_xg[(size_t)TT * BB * G4];   // x_gates [T][B][4H]  (~201 MB)
__device__ float g_h[BB * HH];
__device__ float g_c[BB * HH];
__device__ float g_part[4 * BB * G4];          // k-split partials for step GEMM
__device__ float g_gum[TT * BB * 2];

// ---------------- threefry2x32 (JAX, partitionable path) ----------------
__device__ __forceinline__ uint32_t rotl32(uint32_t v, int s) {
    return (v << s) | (v >> (32 - s));
}
__device__ __forceinline__ void tf_round(uint32_t& x0, uint32_t& x1, int r) {
    x0 += x1; x1 = rotl32(x1, r); x1 ^= x0;
}

__device__ __forceinline__ void threefry2x32(uint32_t k0, uint32_t k1,
                                             uint32_t x0, uint32_t x1,
                                             uint32_t& o0, uint32_t& o1) {
    uint32_t ks0 = k0, ks1 = k1, ks2 = k0 ^ k1 ^ 0x1BD11BDAu;
    x0 += ks0; x1 += ks1;
    tf_round(x0,x1,13); tf_round(x0,x1,15); tf_round(x0,x1,26); tf_round(x0,x1,6);
    x0 += ks1; x1 += ks2 + 1u;
    tf_round(x0,x1,17); tf_round(x0,x1,29); tf_round(x0,x1,16); tf_round(x0,x1,24);
    x0 += ks2; x1 += ks0 + 2u;
    tf_round(x0,x1,13); tf_round(x0,x1,15); tf_round(x0,x1,26); tf_round(x0,x1,6);
    x0 += ks0; x1 += ks1 + 3u;
    tf_round(x0,x1,17); tf_round(x0,x1,29); tf_round(x0,x1,16); tf_round(x0,x1,24);
    x0 += ks1; x1 += ks2 + 4u;
    tf_round(x0,x1,13); tf_round(x0,x1,15); tf_round(x0,x1,26); tf_round(x0,x1,6);
    x0 += ks2; x1 += ks0 + 5u;
    o0 = x0; o1 = x1;
}

// init: zero h/c state, compute gumbel noise table
__global__ void k_init() {
    int i = blockIdx.x * blockDim.x + threadIdx.x;
    if (i < BB * HH) { g_h[i] = 0.0f; g_c[i] = 0.0f; }
    if (i < TT * BB * 2) {
        // jax.random.key(42) -> threefry key (0, 42); partitionable 32-bit bits:
        // (b1,b2) = threefry2x32(key, (hi32(i)=0, lo32(i)=i)); bits = b1 ^ b2
        uint32_t b1, b2;
        threefry2x32(0u, 42u, 0u, (uint32_t)i, b1, b2);
        uint32_t bits = b1 ^ b2;
        uint32_t fb = (bits >> 9) | 0x3F800000u;
        float u = __uint_as_float(fb) - 1.0f;           // uniform [0, 1)
        u = fmaxf(u, 1.17549435e-38f);                  // minval = finfo(f32).tiny
        g_gum[i] = -logf(-logf(u));
    }
}

// ---------------- GEMM 1: x_gates = x @ W_ih^T + b_ih + b_hh ----------------
// C[t*B+b, j] = sum_f feature[b][t][f] * W_ih[j][f] + b_ih[j] + b_hh[j]
// grid (G4/64, T) since BM=64==B; block 128 threads; BK=16; microtile 8x4.
__global__ __launch_bounds__(128) void k_xgates(
    const float* __restrict__ feature, const float* __restrict__ W_ih,
    const float* __restrict__ b_ih, const float* __restrict__ b_hh) {
    __shared__ __align__(16) float As[16][64];
    __shared__ __align__(16) float Bs[16][64];
    const int t  = blockIdx.y;
    const int j0 = blockIdx.x * 64;
    const int tid = threadIdx.x;
    const int tx = tid & 15;   // 0..15 (cols, 4 each)
    const int ty = tid >> 4;   // 0..7  (rows, 8 each)

    float acc[8][4];
#pragma unroll
    for (int m = 0; m < 8; m++)
#pragma unroll
        for (int n = 0; n < 4; n++) acc[m][n] = 0.0f;

    for (int k0 = 0; k0 < FF; k0 += 16) {
#pragma unroll
        for (int l = 0; l < 2; l++) {
            int e   = tid * 2 + l;   // 0..255
            int row = e >> 2;        // 0..63
            int kq  = e & 3;         // 0..3
            // A: x[t][b=row][k] = feature[row][t][k]
            float4 va = *(const float4*)(feature + ((size_t)row * TT + t) * FF + k0 + kq * 4);
            As[kq*4+0][row] = va.x; As[kq*4+1][row] = va.y;
            As[kq*4+2][row] = va.z; As[kq*4+3][row] = va.w;
            // B: W_ih[j0+row][k]
            float4 vb = *(const float4*)(W_ih + (size_t)(j0 + row) * FF + k0 + kq * 4);
            Bs[kq*4+0][row] = vb.x; Bs[kq*4+1][row] = vb.y;
            Bs[kq*4+2][row] = vb.z; Bs[kq*4+3][row] = vb.w;
        }
        __syncthreads();
#pragma unroll
        for (int kk = 0; kk < 16; kk++) {
            float4 a0 = *(const float4*)&As[kk][ty * 8];
            float4 a1 = *(const float4*)&As[kk][ty * 8 + 4];
            float4 bv = *(const float4*)&Bs[kk][tx * 4];
            float a[8] = {a0.x,a0.y,a0.z,a0.w,a1.x,a1.y,a1.z,a1.w};
            float b[4] = {bv.x,bv.y,bv.z,bv.w};
#pragma unroll
            for (int m = 0; m < 8; m++)
#pragma unroll
                for (int n = 0; n < 4; n++)
                    acc[m][n] = fmaf(a[m], b[n], acc[m][n]);
        }
        __syncthreads();
    }

#pragma unroll
    for (int m = 0; m < 8; m++) {
        int b_ = ty * 8 + m;
#pragma unroll
        for (int n = 0; n < 4; n++) {
            int j = j0 + tx * 4 + n;
            g_xg[((size_t)t * BB + b_) * G4 + j] = acc[m][n] + b_ih[j] + b_hh[j];
        }
    }
}

// ---------------- recurrent GEMM (per step): partial = h @ W_hh^T ----------------
// grid (128, 4): bx -> n-tile of 16 gate-columns (x4 gates = 64 j-cols), by -> k-split of 512.
__global__ __launch_bounds__(128) void k_step_gemm(const float* __restrict__ W_hh) {
    __shared__ __align__(16) float As[16][64];
    __shared__ __align__(16) float Bs[16][64];
    const int n0    = blockIdx.x * 16;
    const int kbase = blockIdx.y * 512;
    const int ksl   = blockIdx.y;
    const int tid = threadIdx.x;
    const int tx = tid & 15;
    const int ty = tid >> 4;

    float acc[8][4];
#pragma unroll
    for (int m = 0; m < 8; m++)
#pragma unroll
        for (int n = 0; n < 4; n++) acc[m][n] = 0.0f;

    for (int k0 = 0; k0 < 512; k0 += 16) {
#pragma unroll
        for (int l = 0; l < 2; l++) {
            int e   = tid * 2 + l;
            int row = e >> 2;  // 0..63
            int kq  = e & 3;
            int kg  = kbase + k0 + kq * 4;
            float4 va = *(const float4*)(g_h + (size_t)row * HH + kg);
            As[kq*4+0][row] = va.x; As[kq*4+1][row] = va.y;
            As[kq*4+2][row] = va.z; As[kq*4+3][row] = va.w;
            int q = row >> 4, nn = row & 15;
            int j = q * HH + n0 + nn;      // gate q, column n0+nn
            float4 vb = *(const float4*)(W_hh + (size_t)j * HH + kg);
            Bs[kq*4+0][row] = vb.x; Bs[kq*4+1][row] = vb.y;
            Bs[kq*4+2][row] = vb.z; Bs[kq*4+3][row] = vb.w;
        }
        __syncthreads();
#pragma unroll
        for (int kk = 0; kk < 16; kk++) {
            float4 a0 = *(const float4*)&As[kk][ty * 8];
            float4 a1 = *(const float4*)&As[kk][ty * 8 + 4];
            float4 bv = *(const float4*)&Bs[kk][tx * 4];
            float a[8] = {a0.x,a0.y,a0.z,a0.w,a1.x,a1.y,a1.z,a1.w};
            float b[4] = {bv.x,bv.y,bv.z,bv.w};
#pragma unroll
            for (int m = 0; m < 8; m++)
#pragma unroll
                for (int n = 0; n < 4; n++)
                    acc[m][n] = fmaf(a[m], b[n], acc[m][n]);
        }
        __syncthreads();
    }

#pragma unroll
    for (int m = 0; m < 8; m++) {
        int b_ = ty * 8 + m;
#pragma unroll
        for (int n = 0; n < 4; n++) {
            int c = tx * 4 + n;
            int q = c >> 4, nn = c & 15;
            int j = q * HH + n0 + nn;
            g_part[((size_t)ksl * BB + b_) * G4 + j] = acc[m][n];
        }
    }
}

// ---------------- pointwise LSTM cell update ----------------
__global__ __launch_bounds__(256) void k_step_act(int t) {
    int i = blockIdx.x * 256 + threadIdx.x;   // [0, B*H)
    int b = i >> 11;
    int n = i & (HH - 1);
    size_t base = ((size_t)t * BB + b) * G4;
    float gi = g_xg[base + n];
    float gf = g_xg[base + n + HH];
    float gg = g_xg[base + n + 2*HH];
    float go = g_xg[base + n + 3*HH];
#pragma unroll
    for (int s = 0; s < 4; s++) {
        size_t pb = ((size_t)s * BB + b) * G4;
        gi += g_part[pb + n];
        gf += g_part[pb + n + HH];
        gg += g_part[pb + n + 2*HH];
        go += g_part[pb + n + 3*HH];
    }
    float si = 1.0f / (1.0f + expf(-gi));
    float sf = 1.0f / (1.0f + expf(-gf));
    float so = 1.0f / (1.0f + expf(-go));
    float cv = sf * g_c[i] + si * tanhf(gg);
    float hv = so * tanhf(cv);
    g_c[i] = cv;
    g_h[i] = hv;
}

// ---------------- heads: pred, pred_c, util, use(softmax+gumbel) ----------------
__global__ __launch_bounds__(256) void k_heads(
    int t,
    const float* __restrict__ W_pred,  const float* __restrict__ b_pred,
    const float* __restrict__ W_predc, const float* __restrict__ b_predc,
    const float* __restrict__ W_util,  const float* __restrict__ b_util,
    const float* __restrict__ W_use,   const float* __restrict__ b_use,
    float* __restrict__ out) {
    int b = blockIdx.x;
    int tid = threadIdx.x;
    float s0=0, s1=0, s2=0, s3=0, s4=0, s5=0, s6=0;
    const float* hrow = g_h + (size_t)b * HH;
    const float* crow = g_c + (size_t)b * HH;
    for (int k = tid; k < HH; k += 256) {
        float hv = hrow[k], cv = crow[k];
        s0 += hv * W_pred[k];
        s1 += hv * W_pred[HH + k];
        s2 += cv * W_predc[k];
        s3 += cv * W_predc[HH + k];
        s4 += hv * W_util[k];
        s5 += hv * W_use[k];
        s6 += hv * W_use[HH + k];
    }
#pragma unroll
    for (int off = 16; off > 0; off >>= 1) {
        s0 += __shfl_down_sync(0xffffffffu, s0, off);
        s1 += __shfl_down_sync(0xffffffffu, s1, off);
        s2 += __shfl_down_sync(0xffffffffu, s2, off);
        s3 += __shfl_down_sync(0xffffffffu, s3, off);
        s4 += __shfl_down_sync(0xffffffffu, s4, off);
        s5 += __shfl_down_sync(0xffffffffu, s5, off);
        s6 += __shfl_down_sync(0xffffffffu, s6, off);
    }
    __shared__ float red[8][7];
    int warp = tid >> 5, lane = tid & 31;
    if (lane == 0) {
        red[warp][0]=s0; red[warp][1]=s1; red[warp][2]=s2; red[warp][3]=s3;
        red[warp][4]=s4; red[warp][5]=s5; red[warp][6]=s6;
    }
    __syncthreads();
    if (tid == 0) {
        float r0=0,r1=0,r2=0,r3=0,r4=0,r5=0,r6=0;
#pragma unroll
        for (int w = 0; w < 8; w++) {
            r0+=red[w][0]; r1+=red[w][1]; r2+=red[w][2]; r3+=red[w][3];
            r4+=red[w][4]; r5+=red[w][5]; r6+=red[w][6];
        }
        int tb = t * BB + b;
        out[OFF_HID + tb*2 + 0] = r0 + b_pred[0];
        out[OFF_HID + tb*2 + 1] = r1 + b_pred[1];
        out[OFF_CEL + tb*2 + 0] = r2 + b_predc[0];
        out[OFF_CEL + tb*2 + 1] = r3 + b_predc[1];
        out[OFF_UTL + tb]       = r4 + b_util[0];
        float l0 = r5 + b_use[0] + g_gum[tb*2 + 0];
        float l1 = r6 + b_use[1] + g_gum[tb*2 + 1];
        float m  = fmaxf(l0, l1);
        float e0 = expf(l0 - m), e1 = expf(l1 - m);
        float inv = 1.0f / (e0 + e1);
        if (t > 0) {
            out[OFF_WCH + ((t-1)*BB + b)*2 + 0] = e0 * inv;
            out[OFF_WCH + ((t-1)*BB + b)*2 + 1] = e1 * inv;
        }
    }
}

// ---------------- launch ----------------
extern "C" void kernel_launch(void* const* d_in, const int* in_sizes, int n_in,
                              void* d_out, int out_size) {
    const float* feature = (const float*)d_in[0];
    const float* W_ih    = (const float*)d_in[1];
    const float* W_hh    = (const float*)d_in[2];
    const float* b_ih    = (const float*)d_in[3];
    const float* b_hh    = (const float*)d_in[4];
    const float* W_pred  = (const float*)d_in[5];
    const float* b_pred  = (const float*)d_in[6];
    const float* W_predc = (const float*)d_in[7];
    const float* b_predc = (const float*)d_in[8];
    const float* W_util  = (const float*)d_in[9];
    const float* b_util  = (const float*)d_in[10];
    const float* W_use   = (const float*)d_in[11];
    const float* b_use   = (const float*)d_in[12];
    float* out = (float*)d_out;

    k_init<<<512, 256>>>();

    dim3 g1(G4 / 64, TT);
    k_xgates<<<g1, 128>>>(feature, W_ih, b_ih, b_hh);

    for (int t = 0; t < TT; t++) {
        dim3 gs(128, 4);
        k_step_gemm<<<gs, 128>>>(W_hh);
        k_step_act<<<512, 256>>>(t);
        k_heads<<<64, 256>>>(t, W_pred, b_pred, W_predc, b_predc,
                             W_util, b_util, W_use, b_use, out);
    }
}

// round 4
// speedup vs baseline: 2.1066x; 2.1066x over previous
#include <cuda_runtime.h>
#include <cstdint>
#include <cstddef>

// Problem constants
#define BB 64      // batch
#define TT 96      // time steps
#define FF 2048    // feature dim
#define HH 2048    // hidden dim
#define G4 8192    // 4*H

// Output layout (flattened tuple: hidden(pred), cell(pred_c), utility, watch)
#define OFF_HID 0
#define OFF_CEL (TT*BB*2)            // 12288
#define OFF_UTL (2*TT*BB*2)          // 24576
#define OFF_WCH (2*TT*BB*2 + TT*BB)  // 30720

// ---------------- device scratch (no allocs allowed) ----------------
__device__ float g_xg[(size_t)TT * BB * G4];   // x_gates [T][B][4H] (~201 MB)
__device__ float g_h[BB * HH];
__device__ float g_c[BB * HH];
__device__ float g_part[2 * BB * G4];          // k-split partials (2 splits)
__device__ float g_gum[TT * BB * 2];
__device__ float g_bias[G4];                   // b_ih + b_hh

// ---------------- threefry2x32 (JAX, partitionable path) ----------------
__device__ __forceinline__ uint32_t rotl32(uint32_t v, int s) {
    return (v << s) | (v >> (32 - s));
}
__device__ __forceinline__ void tf_round(uint32_t& x0, uint32_t& x1, int r) {
    x0 += x1; x1 = rotl32(x1, r); x1 ^= x0;
}
__device__ __forceinline__ void threefry2x32(uint32_t k0, uint32_t k1,
                                             uint32_t x0, uint32_t x1,
                                             uint32_t& o0, uint32_t& o1) {
    uint32_t ks0 = k0, ks1 = k1, ks2 = k0 ^ k1 ^ 0x1BD11BDAu;
    x0 += ks0; x1 += ks1;
    tf_round(x0,x1,13); tf_round(x0,x1,15); tf_round(x0,x1,26); tf_round(x0,x1,6);
    x0 += ks1; x1 += ks2 + 1u;
    tf_round(x0,x1,17); tf_round(x0,x1,29); tf_round(x0,x1,16); tf_round(x0,x1,24);
    x0 += ks2; x1 += ks0 + 2u;
    tf_round(x0,x1,13); tf_round(x0,x1,15); tf_round(x0,x1,26); tf_round(x0,x1,6);
    x0 += ks0; x1 += ks1 + 3u;
    tf_round(x0,x1,17); tf_round(x0,x1,29); tf_round(x0,x1,16); tf_round(x0,x1,24);
    x0 += ks1; x1 += ks2 + 4u;
    tf_round(x0,x1,13); tf_round(x0,x1,15); tf_round(x0,x1,26); tf_round(x0,x1,6);
    x0 += ks2; x1 += ks0 + 5u;
    o0 = x0; o1 = x1;
}

// init: zero h/c, gumbel table, fused bias
__global__ void k_init(const float* __restrict__ b_ih, const float* __restrict__ b_hh) {
    int i = blockIdx.x * blockDim.x + threadIdx.x;
    if (i < BB * HH) { g_h[i] = 0.0f; g_c[i] = 0.0f; }
    if (i < G4) g_bias[i] = b_ih[i] + b_hh[i];
    if (i < TT * BB * 2) {
        uint32_t b1, b2;
        threefry2x32(0u, 42u, 0u, (uint32_t)i, b1, b2);
        uint32_t bits = b1 ^ b2;
        uint32_t fb = (bits >> 9) | 0x3F800000u;
        float u = __uint_as_float(fb) - 1.0f;
        u = fmaxf(u, 1.17549435e-38f);
        g_gum[i] = -logf(-logf(u));
    }
}

// ---------------- tf32 MMA helpers ----------------
__device__ __forceinline__ uint32_t f2tf32(float f) {
    uint32_t u;
    asm("cvt.rna.tf32.f32 %0, %1;" : "=r"(u) : "f"(f));
    return u;
}
__device__ __forceinline__ void mma_tf32(float* d, const uint32_t* a,
                                         uint32_t b0, uint32_t b1) {
    asm volatile(
        "mma.sync.aligned.m16n8k8.row.col.f32.tf32.tf32.f32 "
        "{%0,%1,%2,%3}, {%4,%5,%6,%7}, {%8,%9}, {%0,%1,%2,%3};"
        : "+f"(d[0]), "+f"(d[1]), "+f"(d[2]), "+f"(d[3])
        : "r"(a[0]), "r"(a[1]), "r"(a[2]), "r"(a[3]), "r"(b0), "r"(b1));
}

// ---------------- GEMM 1 (tensor core): x_gates = x @ W_ih^T + bias ----------------
// C row r = t*B+b; A[r][k] = feature[b][t][k]; B[j][k] = W_ih[j][k].
// Block tile 128x128, K-tile 16, 256 threads = 8 warps (2M x 4N), warp tile 64x32.
#define XSTR 20   // padded smem stride: (20*m + k) mod 32 distinct -> conflict-free
__global__ __launch_bounds__(256) void k_xgates_mma(
    const float* __restrict__ feature, const float* __restrict__ W_ih) {
    __shared__ uint32_t As[2][128 * XSTR];
    __shared__ uint32_t Bs[2][128 * XSTR];
    const int m0 = blockIdx.y * 128;
    const int j0 = blockIdx.x * 128;
    const int tid = threadIdx.x, lane = tid & 31, wid = tid >> 5;
    const int wm = (wid >> 2) * 64, wn = (wid & 3) * 32;

    float acc[4][4][4];
#pragma unroll
    for (int mi = 0; mi < 4; mi++)
#pragma unroll
        for (int ni = 0; ni < 4; ni++)
#pragma unroll
            for (int q = 0; q < 4; q++) acc[mi][ni][q] = 0.0f;

    float4 ra[2], rb[2];

    // global load of K-tile at k0 into registers
    auto g_load = [&](int k0) {
#pragma unroll
        for (int l = 0; l < 2; l++) {
            int e = tid + l * 256;          // 0..511
            int row = e >> 2, kq = e & 3;
            int r = m0 + row;               // t = r>>6, b = r&63
            ra[l] = *(const float4*)(feature +
                     ((size_t)(r & 63) * TT + (r >> 6)) * FF + k0 + kq * 4);
            rb[l] = *(const float4*)(W_ih + (size_t)(j0 + row) * FF + k0 + kq * 4);
        }
    };
    auto s_store = [&](int buf) {
#pragma unroll
        for (int l = 0; l < 2; l++) {
            int e = tid + l * 256;
            int row = e >> 2, kq = e & 3;
            uint32_t* pa = &As[buf][row * XSTR + kq * 4];
            pa[0] = f2tf32(ra[l].x); pa[1] = f2tf32(ra[l].y);
            pa[2] = f2tf32(ra[l].z); pa[3] = f2tf32(ra[l].w);
            uint32_t* pb = &Bs[buf][row * XSTR + kq * 4];
            pb[0] = f2tf32(rb[l].x); pb[1] = f2tf32(rb[l].y);
            pb[2] = f2tf32(rb[l].z); pb[3] = f2tf32(rb[l].w);
        }
    };

    g_load(0);
    s_store(0);
    const int NKT = FF / 16;   // 128
    for (int kt = 0; kt < NKT; kt++) {
        int buf = kt & 1;
        __syncthreads();
        if (kt + 1 < NKT) g_load((kt + 1) * 16);
#pragma unroll
        for (int ks = 0; ks < 2; ks++) {
            int kk = ks * 8;
            int kcol = kk + (lane & 3);
            uint32_t a[4][4];
#pragma unroll
            for (int mi = 0; mi < 4; mi++) {
                int mrow = wm + mi * 16 + (lane >> 2);
                a[mi][0] = As[buf][mrow * XSTR + kcol];
                a[mi][1] = As[buf][(mrow + 8) * XSTR + kcol];
                a[mi][2] = As[buf][mrow * XSTR + kcol + 4];
                a[mi][3] = As[buf][(mrow + 8) * XSTR + kcol + 4];
            }
#pragma unroll
            for (int ni = 0; ni < 4; ni++) {
                int ncol = wn + ni * 8 + (lane >> 2);
                uint32_t b0 = Bs[buf][ncol * XSTR + kcol];
                uint32_t b1 = Bs[buf][ncol * XSTR + kcol + 4];
#pragma unroll
                for (int mi = 0; mi < 4; mi++)
                    mma_tf32(acc[mi][ni], a[mi], b0, b1);
            }
        }
        if (kt + 1 < NKT) s_store(buf ^ 1);
    }

#pragma unroll
    for (int mi = 0; mi < 4; mi++) {
        int r0 = m0 + wm + mi * 16 + (lane >> 2);
#pragma unroll
        for (int ni = 0; ni < 4; ni++) {
            int j = j0 + wn + ni * 8 + (lane & 3) * 2;
            float bia0 = g_bias[j], bia1 = g_bias[j + 1];
            g_xg[(size_t)r0 * G4 + j]           = acc[mi][ni][0] + bia0;
            g_xg[(size_t)r0 * G4 + j + 1]       = acc[mi][ni][1] + bia1;
            g_xg[(size_t)(r0 + 8) * G4 + j]     = acc[mi][ni][2] + bia0;
            g_xg[(size_t)(r0 + 8) * G4 + j + 1] = acc[mi][ni][3] + bia1;
        }
    }
}

// ---------------- recurrent GEMM (tensor core): partial = h @ W_hh^T ----------------
// grid (64, 2): bx -> 128 contiguous j columns, by -> K-split of 1024.
// 256 threads = 8 warps (4M x 2N), warp tile 16x64.
#define SSTR 20
__global__ __launch_bounds__(256) void k_step_mma(const float* __restrict__ W_hh) {
    __shared__ uint32_t As[2][64 * SSTR];
    __shared__ uint32_t Bs[2][128 * SSTR];
    const int j0 = blockIdx.x * 128;
    const int kbase = blockIdx.y * 1024;
    const int tid = threadIdx.x, lane = tid & 31, wid = tid >> 5;
    const int wm = (wid >> 1) * 16, wn = (wid & 1) * 64;

    float acc[8][4];
#pragma unroll
    for (int ni = 0; ni < 8; ni++)
#pragma unroll
        for (int q = 0; q < 4; q++) acc[ni][q] = 0.0f;

    float4 ra;
    float4 rb[2];
    auto g_load = [&](int k0) {
        {
            int row = tid >> 2, kq = tid & 3;   // 64 rows x 4 quads = 256
            ra = *(const float4*)(g_h + (size_t)row * HH + kbase + k0 + kq * 4);
        }
#pragma unroll
        for (int l = 0; l < 2; l++) {
            int e = tid + l * 256;
            int row = e >> 2, kq = e & 3;
            rb[l] = *(const float4*)(W_hh + (size_t)(j0 + row) * HH + kbase + k0 + kq * 4);
        }
    };
    auto s_store = [&](int buf) {
        {
            int row = tid >> 2, kq = tid & 3;
            uint32_t* pa = &As[buf][row * SSTR + kq * 4];
            pa[0] = f2tf32(ra.x); pa[1] = f2tf32(ra.y);
            pa[2] = f2tf32(ra.z); pa[3] = f2tf32(ra.w);
        }
#pragma unroll
        for (int l = 0; l < 2; l++) {
            int e = tid + l * 256;
            int row = e >> 2, kq = e & 3;
            uint32_t* pb = &Bs[buf][row * SSTR + kq * 4];
            pb[0] = f2tf32(rb[l].x); pb[1] = f2tf32(rb[l].y);
            pb[2] = f2tf32(rb[l].z); pb[3] = f2tf32(rb[l].w);
        }
    };

    g_load(0);
    s_store(0);
    const int NKT = 1024 / 16;   // 64
    for (int kt = 0; kt < NKT; kt++) {
        int buf = kt & 1;
        __syncthreads();
        if (kt + 1 < NKT) g_load((kt + 1) * 16);
#pragma unroll
        for (int ks = 0; ks < 2; ks++) {
            int kk = ks * 8;
            int kcol = kk + (lane & 3);
            int mrow = wm + (lane >> 2);
            uint32_t a[4];
            a[0] = As[buf][mrow * SSTR + kcol];
            a[1] = As[buf][(mrow + 8) * SSTR + kcol];
            a[2] = As[buf][mrow * SSTR + kcol + 4];
            a[3] = As[buf][(mrow + 8) * SSTR + kcol + 4];
#pragma unroll
            for (int ni = 0; ni < 8; ni++) {
                int ncol = wn + ni * 8 + (lane >> 2);
                uint32_t b0 = Bs[buf][ncol * SSTR + kcol];
                uint32_t b1 = Bs[buf][ncol * SSTR + kcol + 4];
                mma_tf32(acc[ni], a, b0, b1);
            }
        }
        if (kt + 1 < NKT) s_store(buf ^ 1);
    }

    int row = wm + (lane >> 2);
    size_t base = (size_t)blockIdx.y * BB;
#pragma unroll
    for (int ni = 0; ni < 8; ni++) {
        int j = j0 + wn + ni * 8 + (lane & 3) * 2;
        *(float2*)&g_part[(base + row) * G4 + j]     = make_float2(acc[ni][0], acc[ni][1]);
        *(float2*)&g_part[(base + row + 8) * G4 + j] = make_float2(acc[ni][2], acc[ni][3]);
    }
}

// ---------------- pointwise LSTM cell update ----------------
__global__ __launch_bounds__(256) void k_step_act(int t) {
    int i = blockIdx.x * 256 + threadIdx.x;   // [0, B*H)
    int b = i >> 11;
    int n = i & (HH - 1);
    size_t base = ((size_t)t * BB + b) * G4;
    float gi = g_xg[base + n];
    float gf = g_xg[base + n + HH];
    float gg = g_xg[base + n + 2*HH];
    float go = g_xg[base + n + 3*HH];
#pragma unroll
    for (int s = 0; s < 2; s++) {
        size_t pb = ((size_t)s * BB + b) * G4;
        gi += g_part[pb + n];
        gf += g_part[pb + n + HH];
        gg += g_part[pb + n + 2*HH];
        go += g_part[pb + n + 3*HH];
    }
    float si = 1.0f / (1.0f + expf(-gi));
    float sf = 1.0f / (1.0f + expf(-gf));
    float so = 1.0f / (1.0f + expf(-go));
    float cv = sf * g_c[i] + si * tanhf(gg);
    float hv = so * tanhf(cv);
    g_c[i] = cv;
    g_h[i] = hv;
}

// ---------------- heads: pred, pred_c, util, use(softmax+gumbel) ----------------
__global__ __launch_bounds__(256) void k_heads(
    int t,
    const float* __restrict__ W_pred,  const float* __restrict__ b_pred,
    const float* __restrict__ W_predc, const float* __restrict__ b_predc,
    const float* __restrict__ W_util,  const float* __restrict__ b_util,
    const float* __restrict__ W_use,   const float* __restrict__ b_use,
    float* __restrict__ out) {
    int b = blockIdx.x;
    int tid = threadIdx.x;
    float s0=0, s1=0, s2=0, s3=0, s4=0, s5=0, s6=0;
    const float* hrow = g_h + (size_t)b * HH;
    const float* crow = g_c + (size_t)b * HH;
    for (int k = tid; k < HH; k += 256) {
        float hv = hrow[k], cv = crow[k];
        s0 += hv * W_pred[k];
        s1 += hv * W_pred[HH + k];
        s2 += cv * W_predc[k];
        s3 += cv * W_predc[HH + k];
        s4 += hv * W_util[k];
        s5 += hv * W_use[k];
        s6 += hv * W_use[HH + k];
    }
#pragma unroll
    for (int off = 16; off > 0; off >>= 1) {
        s0 += __shfl_down_sync(0xffffffffu, s0, off);
        s1 += __shfl_down_sync(0xffffffffu, s1, off);
        s2 += __shfl_down_sync(0xffffffffu, s2, off);
        s3 += __shfl_down_sync(0xffffffffu, s3, off);
        s4 += __shfl_down_sync(0xffffffffu, s4, off);
        s5 += __shfl_down_sync(0xffffffffu, s5, off);
        s6 += __shfl_down_sync(0xffffffffu, s6, off);
    }
    __shared__ float red[8][7];
    int warp = tid >> 5, lane = tid & 31;
    if (lane == 0) {
        red[warp][0]=s0; red[warp][1]=s1; red[warp][2]=s2; red[warp][3]=s3;
        red[warp][4]=s4; red[warp][5]=s5; red[warp][6]=s6;
    }
    __syncthreads();
    if (tid == 0) {
        float r0=0,r1=0,r2=0,r3=0,r4=0,r5=0,r6=0;
#pragma unroll
        for (int w = 0; w < 8; w++) {
            r0+=red[w][0]; r1+=red[w][1]; r2+=red[w][2]; r3+=red[w][3];
            r4+=red[w][4]; r5+=red[w][5]; r6+=red[w][6];
        }
        int tb = t * BB + b;
        out[OFF_HID + tb*2 + 0] = r0 + b_pred[0];
        out[OFF_HID + tb*2 + 1] = r1 + b_pred[1];
        out[OFF_CEL + tb*2 + 0] = r2 + b_predc[0];
        out[OFF_CEL + tb*2 + 1] = r3 + b_predc[1];
        out[OFF_UTL + tb]       = r4 + b_util[0];
        float l0 = r5 + b_use[0] + g_gum[tb*2 + 0];
        float l1 = r6 + b_use[1] + g_gum[tb*2 + 1];
        float m  = fmaxf(l0, l1);
        float e0 = expf(l0 - m), e1 = expf(l1 - m);
        float inv = 1.0f / (e0 + e1);
        if (t > 0) {
            out[OFF_WCH + ((t-1)*BB + b)*2 + 0] = e0 * inv;
            out[OFF_WCH + ((t-1)*BB + b)*2 + 1] = e1 * inv;
        }
    }
}

// ---------------- launch ----------------
extern "C" void kernel_launch(void* const* d_in, const int* in_sizes, int n_in,
                              void* d_out, int out_size) {
    const float* feature = (const float*)d_in[0];
    const float* W_ih    = (const float*)d_in[1];
    const float* W_hh    = (const float*)d_in[2];
    const float* b_ih    = (const float*)d_in[3];
    const float* b_hh    = (const float*)d_in[4];
    const float* W_pred  = (const float*)d_in[5];
    const float* b_pred  = (const float*)d_in[6];
    const float* W_predc = (const float*)d_in[7];
    const float* b_predc = (const float*)d_in[8];
    const float* W_util  = (const float*)d_in[9];
    const float* b_util  = (const float*)d_in[10];
    const float* W_use   = (const float*)d_in[11];
    const float* b_use   = (const float*)d_in[12];
    float* out = (float*)d_out;

    k_init<<<512, 256>>>(b_ih, b_hh);

    dim3 g1(G4 / 128, (TT * BB) / 128);   // (64, 48)
    k_xgates_mma<<<g1, 256>>>(feature, W_ih);

    for (int t = 0; t < TT; t++) {
        dim3 gs(G4 / 128, 2);             // (64, 2)
        k_step_mma<<<gs, 256>>>(W_hh);
        k_step_act<<<512, 256>>>(t);
        k_heads<<<64, 256>>>(t, W_pred, b_pred, W_predc, b_predc,
                             W_util, b_util, W_use, b_use, out);
    }
}